// round 1
// baseline (speedup 1.0000x reference)
#include <cuda_runtime.h>

// Fixed problem shape (SimpleGNN): N=100000 nodes, E=1600000 edges, dims 64->64->64
#define MAXN 100000
#define MAXE 1600000

// Scratch (device globals -- no runtime allocation allowed)
__device__ float g_bufA[MAXN * 64];
__device__ float g_bufB[MAXN * 64];
__device__ int   g_indeg[MAXN];
__device__ int   g_incl[MAXN];
__device__ int   g_offs[MAXN + 1];
__device__ int   g_cursor[MAXN];
__device__ int   g_csr[MAXE];
__device__ float g_dinv[MAXN];
__device__ int   g_bsums[128];

// ---------------------------------------------------------------------------
// CSR build: histogram -> scan -> fill
// ---------------------------------------------------------------------------
__global__ void k_zero(int n) {
    int i = blockIdx.x * blockDim.x + threadIdx.x;
    if (i < n) g_indeg[i] = 0;
}

__global__ void k_hist(const int* __restrict__ dst, int E) {
    int i = blockIdx.x * blockDim.x + threadIdx.x;
    if (i < E) atomicAdd(&g_indeg[dst[i]], 1);
}

// Inclusive scan of indeg per 1024-block; block totals to g_bsums.
__global__ void k_scan1(int n) {
    __shared__ int sh[1024];
    int t = threadIdx.x;
    int i = blockIdx.x * 1024 + t;
    int v = (i < n) ? g_indeg[i] : 0;
    sh[t] = v;
    __syncthreads();
    for (int d = 1; d < 1024; d <<= 1) {
        int u = (t >= d) ? sh[t - d] : 0;
        __syncthreads();
        sh[t] += u;
        __syncthreads();
    }
    if (i < n) g_incl[i] = sh[t];
    if (t == 1023) g_bsums[blockIdx.x] = sh[1023];
}

// Serial exclusive scan of block sums (<=128 entries, trivial).
__global__ void k_scan2(int nb) {
    if (threadIdx.x == 0) {
        int run = 0;
        for (int b = 0; b < nb; b++) {
            int v = g_bsums[b];
            g_bsums[b] = run;
            run += v;
        }
    }
}

// Produce exclusive offsets, cursor copy, dinv = rsqrt(indeg+1) (self-loop).
__global__ void k_scan3(int n) {
    int i = blockIdx.x * blockDim.x + threadIdx.x;
    if (i < n) {
        int ind = g_indeg[i];
        int excl = g_incl[i] - ind + g_bsums[i >> 10];
        g_offs[i] = excl;
        g_cursor[i] = excl;
        g_dinv[i] = rsqrtf((float)(ind + 1));
        if (i == n - 1) g_offs[n] = excl + ind;
    }
}

__global__ void k_fill(const int* __restrict__ src, const int* __restrict__ dst, int E) {
    int i = blockIdx.x * blockDim.x + threadIdx.x;
    if (i < E) {
        int d = dst[i];
        int pos = atomicAdd(&g_cursor[d], 1);
        g_csr[pos] = src[i];
    }
}

// ---------------------------------------------------------------------------
// GEMM: Y[n,64] = X[n,64] @ W[64,64]. 128 threads/block, 128 rows/block.
// Each thread computes an 8x8 register tile.
// ---------------------------------------------------------------------------
__global__ __launch_bounds__(128) void k_gemm64(const float* __restrict__ X,
                                                const float* __restrict__ W,
                                                float* __restrict__ Y, int n) {
    __shared__ float Ws[64 * 64];
    __shared__ float Xs[128 * 65];  // pad 65 to avoid bank conflicts

    int t = threadIdx.x;
    #pragma unroll
    for (int i = t; i < 4096; i += 128) Ws[i] = W[i];

    int row0 = blockIdx.x * 128;
    for (int i = t; i < 8192; i += 128) {
        int r = i >> 6, c = i & 63;
        int gr = row0 + r;
        Xs[r * 65 + c] = (gr < n) ? X[gr * 64 + c] : 0.f;
    }
    __syncthreads();

    int cg = t & 7;       // column group: cols [cg*8, cg*8+8)
    int rg = t >> 3;      // row group:    rows [rg*8, rg*8+8)

    float acc[8][8];
    #pragma unroll
    for (int i = 0; i < 8; i++)
        #pragma unroll
        for (int j = 0; j < 8; j++) acc[i][j] = 0.f;

    #pragma unroll 8
    for (int k = 0; k < 64; k++) {
        float4 w0 = *(const float4*)&Ws[k * 64 + cg * 8];
        float4 w1 = *(const float4*)&Ws[k * 64 + cg * 8 + 4];
        float xv[8];
        #pragma unroll
        for (int i = 0; i < 8; i++) xv[i] = Xs[(rg * 8 + i) * 65 + k];
        #pragma unroll
        for (int i = 0; i < 8; i++) {
            acc[i][0] = fmaf(xv[i], w0.x, acc[i][0]);
            acc[i][1] = fmaf(xv[i], w0.y, acc[i][1]);
            acc[i][2] = fmaf(xv[i], w0.z, acc[i][2]);
            acc[i][3] = fmaf(xv[i], w0.w, acc[i][3]);
            acc[i][4] = fmaf(xv[i], w1.x, acc[i][4]);
            acc[i][5] = fmaf(xv[i], w1.y, acc[i][5]);
            acc[i][6] = fmaf(xv[i], w1.z, acc[i][6]);
            acc[i][7] = fmaf(xv[i], w1.w, acc[i][7]);
        }
    }

    #pragma unroll
    for (int i = 0; i < 8; i++) {
        int gr = row0 + rg * 8 + i;
        if (gr < n) {
            float4* o = (float4*)&Y[gr * 64 + cg * 8];
            o[0] = make_float4(acc[i][0], acc[i][1], acc[i][2], acc[i][3]);
            o[1] = make_float4(acc[i][4], acc[i][5], acc[i][6], acc[i][7]);
        }
    }
}

// ---------------------------------------------------------------------------
// Pull-mode aggregation: out[v] = relu( sum_{e in csr(v)} xw[src]*dinv[src]*dinv[v]
//                                       + xw[v]*dinv[v]^2 + bias )
// One warp per node; lane owns float2 columns [2*lane, 2*lane+1].
// ---------------------------------------------------------------------------
__global__ __launch_bounds__(256) void k_agg(const float* __restrict__ XW,
                                             const float* __restrict__ bias,
                                             float* __restrict__ out, int n) {
    int warp = (blockIdx.x * 256 + threadIdx.x) >> 5;
    int lane = threadIdx.x & 31;
    if (warp >= n) return;
    int v = warp;
    float dv = g_dinv[v];

    const float2* xw2 = (const float2*)XW;
    float2 sf = xw2[v * 32 + lane];
    float sw = dv * dv;  // self-loop norm
    float ax = sf.x * sw, ay = sf.y * sw;

    int e = g_offs[v];
    int end = g_offs[v + 1];

    // full 32-edge batches
    for (; e + 32 <= end; e += 32) {
        int s = g_csr[e + lane];
        float ds = g_dinv[s];
        #pragma unroll
        for (int j = 0; j < 32; j++) {
            int sj = __shfl_sync(0xffffffffu, s, j);
            float nj = __shfl_sync(0xffffffffu, ds, j) * dv;
            float2 m = xw2[sj * 32 + lane];
            ax = fmaf(m.x, nj, ax);
            ay = fmaf(m.y, nj, ay);
        }
    }
    // tail (< 32 edges)
    int rem = end - e;
    if (rem > 0) {
        int s = 0;
        float ds = 0.f;
        if (lane < rem) {
            s = g_csr[e + lane];
            ds = g_dinv[s];
        }
        for (int j = 0; j < rem; j++) {
            int sj = __shfl_sync(0xffffffffu, s, j);
            float nj = __shfl_sync(0xffffffffu, ds, j) * dv;
            float2 m = xw2[sj * 32 + lane];
            ax = fmaf(m.x, nj, ax);
            ay = fmaf(m.y, nj, ay);
        }
    }

    float bx = bias[lane * 2], by = bias[lane * 2 + 1];
    float2 r;
    r.x = fmaxf(ax + bx, 0.f);
    r.y = fmaxf(ay + by, 0.f);
    ((float2*)out)[v * 32 + lane] = r;
}

// ---------------------------------------------------------------------------
extern "C" void kernel_launch(void* const* d_in, const int* in_sizes, int n_in,
                              void* d_out, int out_size) {
    const float* x  = (const float*)d_in[0];
    const int*   ei = (const int*)d_in[1];
    const float* W1 = (const float*)d_in[2];
    const float* b1 = (const float*)d_in[3];
    const float* W2 = (const float*)d_in[4];
    const float* b2 = (const float*)d_in[5];
    float* out = (float*)d_out;

    int N = in_sizes[0] / 64;
    int E = in_sizes[1] / 2;
    const int* src = ei;
    const int* dst = ei + E;

    int nbN = (N + 255) / 256;
    int nbE = (E + 255) / 256;
    int nbScan = (N + 1023) / 1024;
    int nbAgg = (N + 7) / 8;       // 8 warps per 256-thread block
    int nbGemm = (N + 127) / 128;

    // CSR build (per launch -- deterministic work each call)
    k_zero<<<nbN, 256>>>(N);
    k_hist<<<nbE, 256>>>(dst, E);
    k_scan1<<<nbScan, 1024>>>(N);
    k_scan2<<<1, 32>>>(nbScan);
    k_scan3<<<nbN, 256>>>(N);
    k_fill<<<nbE, 256>>>(src, dst, E);

    // Layer 1: h = relu(Agg(x @ W1) + b1)
    float* bufA;  cudaGetSymbolAddress((void**)&bufA, g_bufA);
    float* bufB;  cudaGetSymbolAddress((void**)&bufB, g_bufB);

    k_gemm64<<<nbGemm, 128>>>(x, W1, bufA, N);
    k_agg<<<nbAgg, 256>>>(bufA, b1, bufB, N);

    // Layer 2: out = relu(Agg(h @ W2) + b2)
    k_gemm64<<<nbGemm, 128>>>(bufB, W2, bufA, N);
    k_agg<<<nbAgg, 256>>>(bufA, b2, out, N);
}

// round 2
// speedup vs baseline: 1.0108x; 1.0108x over previous
#include <cuda_runtime.h>

// Fixed problem shape (SimpleGNN): N=100000 nodes, E=1600000 edges, dims 64->64->64
#define MAXN 100000
#define MAXE 1600000

// Scratch (device globals -- no runtime allocation allowed)
__device__ float g_bufA[MAXN * 64];
__device__ float g_bufB[MAXN * 64];
__device__ int   g_indeg[MAXN];
__device__ int   g_incl[MAXN];
__device__ int   g_offs[MAXN + 1];
__device__ int   g_cursor[MAXN];
__device__ int   g_csr[MAXE];
__device__ float g_csrw[MAXE];      // per-edge weight = dinv[src]
__device__ float g_dinv[MAXN];
__device__ int   g_bsums[128];

// ---------------------------------------------------------------------------
// f32x2 packed-FMA helpers (sm_10x FFMA2 -- only reachable via PTX)
// ---------------------------------------------------------------------------
__device__ __forceinline__ void ffma2(unsigned long long& acc,
                                      unsigned long long a, unsigned long long b) {
    asm("fma.rn.f32x2 %0, %1, %2, %0;" : "+l"(acc) : "l"(a), "l"(b));
}
__device__ __forceinline__ unsigned long long pack2(float v) {
    unsigned long long r;
    asm("mov.b64 %0, {%1, %1};" : "=l"(r) : "f"(v));
    return r;
}
__device__ __forceinline__ float2 unpack2(unsigned long long v) {
    float2 r;
    asm("mov.b64 {%0, %1}, %2;" : "=f"(r.x), "=f"(r.y) : "l"(v));
    return r;
}

// ---------------------------------------------------------------------------
// CSR build: histogram -> scan -> fill (with fused edge weights)
// ---------------------------------------------------------------------------
__global__ void k_hist(const int* __restrict__ dst, int E) {
    int i = blockIdx.x * blockDim.x + threadIdx.x;
    if (i < E) atomicAdd(&g_indeg[dst[i]], 1);
}

// Inclusive scan of indeg per 1024-block; block totals to g_bsums.
__global__ void k_scan1(int n) {
    __shared__ int sh[1024];
    int t = threadIdx.x;
    int i = blockIdx.x * 1024 + t;
    int v = (i < n) ? g_indeg[i] : 0;
    sh[t] = v;
    __syncthreads();
    for (int d = 1; d < 1024; d <<= 1) {
        int u = (t >= d) ? sh[t - d] : 0;
        __syncthreads();
        sh[t] += u;
        __syncthreads();
    }
    if (i < n) g_incl[i] = sh[t];
    if (t == 1023) g_bsums[blockIdx.x] = sh[1023];
}

// Parallel exclusive scan of <=128 block sums (1 block, 128 threads).
__global__ void k_scan2(int nb) {
    int t = threadIdx.x;
    int lane = t & 31, w = t >> 5;
    int v = (t < nb) ? g_bsums[t] : 0;
    int x = v;
    #pragma unroll
    for (int d = 1; d < 32; d <<= 1) {
        int y = __shfl_up_sync(0xffffffffu, x, d);
        if (lane >= d) x += y;
    }
    __shared__ int wt[4];
    if (lane == 31) wt[w] = x;
    __syncthreads();
    int add = 0;
    for (int k = 0; k < w; k++) add += wt[k];
    x += add;
    if (t < nb) g_bsums[t] = x - v;   // exclusive
}

// Produce exclusive offsets, cursor copy, dinv = rsqrt(indeg+1) (self-loop).
__global__ void k_scan3(int n) {
    int i = blockIdx.x * blockDim.x + threadIdx.x;
    if (i < n) {
        int ind = g_indeg[i];
        int excl = g_incl[i] - ind + g_bsums[i >> 10];
        g_offs[i] = excl;
        g_cursor[i] = excl;
        g_dinv[i] = rsqrtf((float)(ind + 1));
        if (i == n - 1) g_offs[n] = excl + ind;
    }
}

__global__ void k_fill(const int* __restrict__ src, const int* __restrict__ dst, int E) {
    int i = blockIdx.x * blockDim.x + threadIdx.x;
    if (i < E) {
        int d = dst[i];
        int s = src[i];
        int pos = atomicAdd(&g_cursor[d], 1);
        g_csr[pos] = s;
        g_csrw[pos] = g_dinv[s];
    }
}

// ---------------------------------------------------------------------------
// GEMM: Y[n,64] = X[n,64] @ W[64,64]. 128 threads/block, 128 rows/block.
// Each thread computes an 8x8 tile via packed f32x2 FMA (4 FFMA2/row/k).
// ---------------------------------------------------------------------------
__global__ __launch_bounds__(128) void k_gemm64(const float* __restrict__ X,
                                                const float* __restrict__ W,
                                                float* __restrict__ Y, int n) {
    __shared__ float Ws[64 * 64];
    __shared__ float Xs[128 * 65];  // pad to 65 to avoid bank conflicts

    int t = threadIdx.x;
    #pragma unroll
    for (int i = t; i < 4096; i += 128) Ws[i] = W[i];

    int row0 = blockIdx.x * 128;
    for (int i = t; i < 8192; i += 128) {
        int r = i >> 6, c = i & 63;
        int gr = row0 + r;
        Xs[r * 65 + c] = (gr < n) ? X[gr * 64 + c] : 0.f;
    }
    __syncthreads();

    int cg = t & 7;       // column group: cols [cg*8, cg*8+8)
    int rg = t >> 3;      // row group:    rows [rg*8, rg*8+8)

    unsigned long long acc[8][4];
    #pragma unroll
    for (int i = 0; i < 8; i++)
        #pragma unroll
        for (int j = 0; j < 4; j++) acc[i][j] = 0ull;

    #pragma unroll 4
    for (int k = 0; k < 64; k++) {
        // 8 weight cols as 4 packed f32x2 (16B-aligned in smem)
        ulonglong2 wA = *(const ulonglong2*)&Ws[k * 64 + cg * 8];
        ulonglong2 wB = *(const ulonglong2*)&Ws[k * 64 + cg * 8 + 4];
        #pragma unroll
        for (int i = 0; i < 8; i++) {
            unsigned long long xp = pack2(Xs[(rg * 8 + i) * 65 + k]);
            ffma2(acc[i][0], xp, wA.x);
            ffma2(acc[i][1], xp, wA.y);
            ffma2(acc[i][2], xp, wB.x);
            ffma2(acc[i][3], xp, wB.y);
        }
    }

    #pragma unroll
    for (int i = 0; i < 8; i++) {
        int gr = row0 + rg * 8 + i;
        if (gr < n) {
            float2 p0 = unpack2(acc[i][0]), p1 = unpack2(acc[i][1]);
            float2 p2 = unpack2(acc[i][2]), p3 = unpack2(acc[i][3]);
            float4* o = (float4*)&Y[gr * 64 + cg * 8];
            o[0] = make_float4(p0.x, p0.y, p1.x, p1.y);
            o[1] = make_float4(p2.x, p2.y, p3.x, p3.y);
        }
    }
}

// ---------------------------------------------------------------------------
// Pull-mode aggregation: out[v] = relu( sum_e xw[csr[e]] * csrw[e]*dinv[v]
//                                       + xw[v]*dinv[v]^2 + bias )
// One warp per node; lane owns float2 columns [2*lane, 2*lane+1].
// Edge index/weight are uniform broadcast loads (no shfl chain); unroll x4
// gives MLP=4 on the 256B row gathers.
// ---------------------------------------------------------------------------
__global__ __launch_bounds__(256) void k_agg(const float* __restrict__ XW,
                                             const float* __restrict__ bias,
                                             float* __restrict__ out, int n) {
    int v = (blockIdx.x * 256 + threadIdx.x) >> 5;
    int lane = threadIdx.x & 31;
    if (v >= n) return;
    float dv = g_dinv[v];

    const float2* __restrict__ xw2 = (const float2*)XW;
    float2 sf = __ldg(&xw2[v * 32 + lane]);
    float sw = dv * dv;  // self-loop norm
    float ax = sf.x * sw, ay = sf.y * sw;

    int e = g_offs[v];
    int end = g_offs[v + 1];
    int e4 = e + ((end - e) & ~3);

    for (; e < e4; e += 4) {
        int s0 = __ldg(&g_csr[e]);
        int s1 = __ldg(&g_csr[e + 1]);
        int s2 = __ldg(&g_csr[e + 2]);
        int s3 = __ldg(&g_csr[e + 3]);
        float w0 = __ldg(&g_csrw[e])     * dv;
        float w1 = __ldg(&g_csrw[e + 1]) * dv;
        float w2 = __ldg(&g_csrw[e + 2]) * dv;
        float w3 = __ldg(&g_csrw[e + 3]) * dv;
        float2 m0 = __ldg(&xw2[s0 * 32 + lane]);
        float2 m1 = __ldg(&xw2[s1 * 32 + lane]);
        float2 m2 = __ldg(&xw2[s2 * 32 + lane]);
        float2 m3 = __ldg(&xw2[s3 * 32 + lane]);
        ax = fmaf(m0.x, w0, ax);  ay = fmaf(m0.y, w0, ay);
        ax = fmaf(m1.x, w1, ax);  ay = fmaf(m1.y, w1, ay);
        ax = fmaf(m2.x, w2, ax);  ay = fmaf(m2.y, w2, ay);
        ax = fmaf(m3.x, w3, ax);  ay = fmaf(m3.y, w3, ay);
    }
    for (; e < end; e++) {
        int s = __ldg(&g_csr[e]);
        float w = __ldg(&g_csrw[e]) * dv;
        float2 m = __ldg(&xw2[s * 32 + lane]);
        ax = fmaf(m.x, w, ax);
        ay = fmaf(m.y, w, ay);
    }

    float bx = __ldg(&bias[lane * 2]), by = __ldg(&bias[lane * 2 + 1]);
    float2 r;
    r.x = fmaxf(ax + bx, 0.f);
    r.y = fmaxf(ay + by, 0.f);
    ((float2*)out)[v * 32 + lane] = r;
}

// ---------------------------------------------------------------------------
extern "C" void kernel_launch(void* const* d_in, const int* in_sizes, int n_in,
                              void* d_out, int out_size) {
    const float* x  = (const float*)d_in[0];
    const int*   ei = (const int*)d_in[1];
    const float* W1 = (const float*)d_in[2];
    const float* b1 = (const float*)d_in[3];
    const float* W2 = (const float*)d_in[4];
    const float* b2 = (const float*)d_in[5];
    float* out = (float*)d_out;

    int N = in_sizes[0] / 64;
    int E = in_sizes[1] / 2;
    const int* src = ei;
    const int* dst = ei + E;

    int nbN = (N + 255) / 256;
    int nbE = (E + 255) / 256;
    int nbScan = (N + 1023) / 1024;
    int nbAgg = (N + 7) / 8;       // 8 warps per 256-thread block
    int nbGemm = (N + 127) / 128;

    void* indegPtr;  cudaGetSymbolAddress(&indegPtr, g_indeg);
    float* bufA;     cudaGetSymbolAddress((void**)&bufA, g_bufA);
    float* bufB;     cudaGetSymbolAddress((void**)&bufB, g_bufB);

    // CSR build (per launch -- deterministic work each call)
    cudaMemsetAsync(indegPtr, 0, (size_t)N * sizeof(int));
    k_hist<<<nbE, 256>>>(dst, E);
    k_scan1<<<nbScan, 1024>>>(N);
    k_scan2<<<1, 128>>>(nbScan);
    k_scan3<<<nbN, 256>>>(N);
    k_fill<<<nbE, 256>>>(src, dst, E);

    // Layer 1: h = relu(Agg(x @ W1) + b1)
    k_gemm64<<<nbGemm, 128>>>(x, W1, bufA, N);
    k_agg<<<nbAgg, 256>>>(bufA, b1, bufB, N);

    // Layer 2: out = relu(Agg(h @ W2) + b2)
    k_gemm64<<<nbGemm, 128>>>(bufB, W2, bufA, N);
    k_agg<<<nbAgg, 256>>>(bufA, b2, out, N);
}

// round 4
// speedup vs baseline: 1.1084x; 1.0966x over previous
#include <cuda_runtime.h>
#include <cuda_fp16.h>

// Fixed problem shape (SimpleGNN): N=100000 nodes, E=1600000 edges, dims 64->64->64
#define MAXN 100000
#define MAXE 1600000

// Scratch (device globals -- no runtime allocation allowed)
__device__ __half g_hbuf[MAXN * 64];   // fp16 message table (gathered by agg)
__device__ float  g_bufB[MAXN * 64];   // fp32 hidden activations
__device__ int    g_indeg[MAXN];
__device__ int    g_incl[MAXN];
__device__ int    g_offs[MAXN + 1];
__device__ int    g_cursor[MAXN];
__device__ int2   g_csrp[MAXE];        // (src_idx, bitcast(dinv[src]))
__device__ float  g_dinv[MAXN];
__device__ int    g_bsums[128];

// ---------------------------------------------------------------------------
// f32x2 packed-FMA helpers (sm_10x FFMA2 -- only reachable via PTX)
// ---------------------------------------------------------------------------
__device__ __forceinline__ void ffma2(unsigned long long& acc,
                                      unsigned long long a, unsigned long long b) {
    asm("fma.rn.f32x2 %0, %1, %2, %0;" : "+l"(acc) : "l"(a), "l"(b));
}
__device__ __forceinline__ unsigned long long pack2(float v) {
    unsigned long long r;
    asm("mov.b64 %0, {%1, %1};" : "=l"(r) : "f"(v));
    return r;
}
__device__ __forceinline__ float2 unpack2(unsigned long long v) {
    float2 r;
    asm("mov.b64 {%0, %1}, %2;" : "=f"(r.x), "=f"(r.y) : "l"(v));
    return r;
}
__device__ __forceinline__ unsigned h2_bits(__half2 h) {
    return *reinterpret_cast<unsigned*>(&h);
}

// ---------------------------------------------------------------------------
// CSR build: histogram -> scan -> fill (packed idx+weight)
// ---------------------------------------------------------------------------
__global__ void k_hist(const int* __restrict__ dst, int E) {
    int i = blockIdx.x * blockDim.x + threadIdx.x;
    if (i < E) atomicAdd(&g_indeg[dst[i]], 1);
}

// Inclusive scan of indeg per 1024-block (shfl-based); block totals to g_bsums.
__global__ void k_scan1(int n) {
    __shared__ int wsum[32];
    int t = threadIdx.x, lane = t & 31, w = t >> 5;
    int i = blockIdx.x * 1024 + t;
    int v = (i < n) ? g_indeg[i] : 0;
    int x = v;
    #pragma unroll
    for (int d = 1; d < 32; d <<= 1) {
        int y = __shfl_up_sync(0xffffffffu, x, d);
        if (lane >= d) x += y;
    }
    if (lane == 31) wsum[w] = x;
    __syncthreads();
    if (w == 0) {
        int y = wsum[lane];
        int z = y;
        #pragma unroll
        for (int d = 1; d < 32; d <<= 1) {
            int u = __shfl_up_sync(0xffffffffu, z, d);
            if (lane >= d) z += u;
        }
        wsum[lane] = z - y;  // exclusive
    }
    __syncthreads();
    x += wsum[w];
    if (i < n) g_incl[i] = x;
    if (t == 1023) g_bsums[blockIdx.x] = x;
}

// Parallel exclusive scan of <=128 block sums (1 block, 128 threads).
__global__ void k_scan2(int nb) {
    int t = threadIdx.x;
    int lane = t & 31, w = t >> 5;
    int v = (t < nb) ? g_bsums[t] : 0;
    int x = v;
    #pragma unroll
    for (int d = 1; d < 32; d <<= 1) {
        int y = __shfl_up_sync(0xffffffffu, x, d);
        if (lane >= d) x += y;
    }
    __shared__ int wt[4];
    if (lane == 31) wt[w] = x;
    __syncthreads();
    int add = 0;
    for (int k = 0; k < w; k++) add += wt[k];
    x += add;
    if (t < nb) g_bsums[t] = x - v;   // exclusive
}

// Produce exclusive offsets, cursor copy, dinv = rsqrt(indeg+1) (self-loop).
__global__ void k_scan3(int n) {
    int i = blockIdx.x * blockDim.x + threadIdx.x;
    if (i < n) {
        int ind = g_indeg[i];
        int excl = g_incl[i] - ind + g_bsums[i >> 10];
        g_offs[i] = excl;
        g_cursor[i] = excl;
        g_dinv[i] = rsqrtf((float)(ind + 1));
        if (i == n - 1) g_offs[n] = excl + ind;
    }
}

__global__ void k_fill(const int* __restrict__ src, const int* __restrict__ dst, int E) {
    int i = blockIdx.x * blockDim.x + threadIdx.x;
    if (i < E) {
        int d = dst[i];
        int s = src[i];
        int pos = atomicAdd(&g_cursor[d], 1);
        g_csrp[pos] = make_int2(s, __float_as_int(g_dinv[s]));
    }
}

// ---------------------------------------------------------------------------
// GEMM: Yh[n,64] (fp16) = X[n,64] @ W[64,64] (fp32 compute, fp16 store).
// 128 threads/block, 128 rows/block; 8x8 tile/thread via packed f32x2 FMA.
// ---------------------------------------------------------------------------
__global__ __launch_bounds__(128) void k_gemm64h(const float* __restrict__ X,
                                                 const float* __restrict__ W,
                                                 __half* __restrict__ Yh, int n) {
    __shared__ float Ws[64 * 64];
    __shared__ float Xs[128 * 65];  // pad to 65 to avoid bank conflicts

    int t = threadIdx.x;
    #pragma unroll
    for (int i = t; i < 4096; i += 128) Ws[i] = W[i];

    int row0 = blockIdx.x * 128;
    for (int i = t; i < 8192; i += 128) {
        int r = i >> 6, c = i & 63;
        int gr = row0 + r;
        Xs[r * 65 + c] = (gr < n) ? X[gr * 64 + c] : 0.f;
    }
    __syncthreads();

    int cg = t & 7;       // column group: cols [cg*8, cg*8+8)
    int rg = t >> 3;      // row group:    rows [rg*8, rg*8+8)

    unsigned long long acc[8][4];
    #pragma unroll
    for (int i = 0; i < 8; i++)
        #pragma unroll
        for (int j = 0; j < 4; j++) acc[i][j] = 0ull;

    #pragma unroll 4
    for (int k = 0; k < 64; k++) {
        ulonglong2 wA = *(const ulonglong2*)&Ws[k * 64 + cg * 8];
        ulonglong2 wB = *(const ulonglong2*)&Ws[k * 64 + cg * 8 + 4];
        #pragma unroll
        for (int i = 0; i < 8; i++) {
            unsigned long long xp = pack2(Xs[(rg * 8 + i) * 65 + k]);
            ffma2(acc[i][0], xp, wA.x);
            ffma2(acc[i][1], xp, wA.y);
            ffma2(acc[i][2], xp, wB.x);
            ffma2(acc[i][3], xp, wB.y);
        }
    }

    #pragma unroll
    for (int i = 0; i < 8; i++) {
        int gr = row0 + rg * 8 + i;
        if (gr < n) {
            float2 p0 = unpack2(acc[i][0]), p1 = unpack2(acc[i][1]);
            float2 p2 = unpack2(acc[i][2]), p3 = unpack2(acc[i][3]);
            uint4 pk;
            pk.x = h2_bits(__floats2half2_rn(p0.x, p0.y));
            pk.y = h2_bits(__floats2half2_rn(p1.x, p1.y));
            pk.z = h2_bits(__floats2half2_rn(p2.x, p2.y));
            pk.w = h2_bits(__floats2half2_rn(p3.x, p3.y));
            *(uint4*)&Yh[gr * 64 + cg * 8] = pk;
        }
    }
}

// ---------------------------------------------------------------------------
// Pull-mode aggregation from fp16 message table, fp32 accumulate.
// out[v] = relu( sum_e xwh[csr[e].s] * csr[e].w * dinv[v]
//                + xwh[v]*dinv[v]^2 + bias )
// One warp per node; lane owns half2 columns [2*lane, 2*lane+1] (128B/warp/edge).
// ---------------------------------------------------------------------------
__global__ __launch_bounds__(256) void k_agg(const __half2* __restrict__ xwh,
                                             const float* __restrict__ bias,
                                             float* __restrict__ out, int n) {
    int v = (blockIdx.x * 256 + threadIdx.x) >> 5;
    int lane = threadIdx.x & 31;
    if (v >= n) return;
    float dv = g_dinv[v];

    float2 sf = __half22float2(__ldg(&xwh[v * 32 + lane]));
    float sw = dv * dv;  // self-loop norm
    float ax = sf.x * sw, ay = sf.y * sw;

    int e = g_offs[v];
    int end = g_offs[v + 1];
    int e4 = e + ((end - e) & ~3);

    for (; e < e4; e += 4) {
        int2 p0 = __ldg(&g_csrp[e]);
        int2 p1 = __ldg(&g_csrp[e + 1]);
        int2 p2 = __ldg(&g_csrp[e + 2]);
        int2 p3 = __ldg(&g_csrp[e + 3]);
        float w0 = __int_as_float(p0.y) * dv;
        float w1 = __int_as_float(p1.y) * dv;
        float w2 = __int_as_float(p2.y) * dv;
        float w3 = __int_as_float(p3.y) * dv;
        float2 m0 = __half22float2(__ldg(&xwh[p0.x * 32 + lane]));
        float2 m1 = __half22float2(__ldg(&xwh[p1.x * 32 + lane]));
        float2 m2 = __half22float2(__ldg(&xwh[p2.x * 32 + lane]));
        float2 m3 = __half22float2(__ldg(&xwh[p3.x * 32 + lane]));
        ax = fmaf(m0.x, w0, ax);  ay = fmaf(m0.y, w0, ay);
        ax = fmaf(m1.x, w1, ax);  ay = fmaf(m1.y, w1, ay);
        ax = fmaf(m2.x, w2, ax);  ay = fmaf(m2.y, w2, ay);
        ax = fmaf(m3.x, w3, ax);  ay = fmaf(m3.y, w3, ay);
    }
    for (; e < end; e++) {
        int2 p = __ldg(&g_csrp[e]);
        float w = __int_as_float(p.y) * dv;
        float2 m = __half22float2(__ldg(&xwh[p.x * 32 + lane]));
        ax = fmaf(m.x, w, ax);
        ay = fmaf(m.y, w, ay);
    }

    float bx = __ldg(&bias[lane * 2]), by = __ldg(&bias[lane * 2 + 1]);
    float2 r;
    r.x = fmaxf(ax + bx, 0.f);
    r.y = fmaxf(ay + by, 0.f);
    ((float2*)out)[v * 32 + lane] = r;
}

// ---------------------------------------------------------------------------
extern "C" void kernel_launch(void* const* d_in, const int* in_sizes, int n_in,
                              void* d_out, int out_size) {
    const float* x  = (const float*)d_in[0];
    const int*   ei = (const int*)d_in[1];
    const float* W1 = (const float*)d_in[2];
    const float* b1 = (const float*)d_in[3];
    const float* W2 = (const float*)d_in[4];
    const float* b2 = (const float*)d_in[5];
    float* out = (float*)d_out;

    int N = in_sizes[0] / 64;
    int E = in_sizes[1] / 2;
    const int* src = ei;
    const int* dst = ei + E;

    int nbN = (N + 255) / 256;
    int nbE = (E + 255) / 256;
    int nbScan = (N + 1023) / 1024;
    int nbAgg = (N + 7) / 8;       // 8 warps per 256-thread block
    int nbGemm = (N + 127) / 128;

    void* indegPtr;     cudaGetSymbolAddress(&indegPtr, g_indeg);
    __half* hbuf;       cudaGetSymbolAddress((void**)&hbuf, g_hbuf);
    float* bufB;        cudaGetSymbolAddress((void**)&bufB, g_bufB);

    // CSR build (per launch -- deterministic work each call)
    cudaMemsetAsync(indegPtr, 0, (size_t)N * sizeof(int));
    k_hist<<<nbE, 256>>>(dst, E);
    k_scan1<<<nbScan, 1024>>>(N);
    k_scan2<<<1, 128>>>(nbScan);
    k_scan3<<<nbN, 256>>>(N);
    k_fill<<<nbE, 256>>>(src, dst, E);

    // Layer 1: h = relu(Agg(x @ W1) + b1)
    k_gemm64h<<<nbGemm, 128>>>(x, W1, hbuf, N);
    k_agg<<<nbAgg, 256>>>((const __half2*)hbuf, b1, bufB, N);

    // Layer 2: out = relu(Agg(h @ W2) + b2)
    k_gemm64h<<<nbGemm, 128>>>(bufB, W2, hbuf, N);
    k_agg<<<nbAgg, 256>>>((const __half2*)hbuf, b2, out, N);
}

// round 5
// speedup vs baseline: 1.1795x; 1.0641x over previous
#include <cuda_runtime.h>
#include <cuda_fp16.h>

// Fixed problem shape (SimpleGNN): N=100000 nodes, E=1600000 edges, dims 64->64->64
#define MAXN 100000
#define MAXE 1600000

// Scratch (device globals -- no runtime allocation allowed)
__device__ __half g_hbuf[MAXN * 64];   // fp16 pre-scaled message table
__device__ float  g_bufB[MAXN * 64];   // fp32 hidden activations
__device__ int    g_indeg[MAXN];
__device__ int    g_incl[MAXN];
__device__ int    g_offs[MAXN];        // exclusive offsets; shifted to ends by k_fill
__device__ int    g_csr[MAXE];         // src index only (weight folded into message)
__device__ float  g_dinv[MAXN];
__device__ int    g_bsums[128];

// ---------------------------------------------------------------------------
// f32x2 packed-FMA helpers (sm_10x FFMA2 -- only reachable via PTX)
// ---------------------------------------------------------------------------
__device__ __forceinline__ void ffma2(unsigned long long& acc,
                                      unsigned long long a, unsigned long long b) {
    asm("fma.rn.f32x2 %0, %1, %2, %0;" : "+l"(acc) : "l"(a), "l"(b));
}
__device__ __forceinline__ unsigned long long pack2(float v) {
    unsigned long long r;
    asm("mov.b64 %0, {%1, %1};" : "=l"(r) : "f"(v));
    return r;
}
__device__ __forceinline__ float2 unpack2(unsigned long long v) {
    float2 r;
    asm("mov.b64 {%0, %1}, %2;" : "=f"(r.x), "=f"(r.y) : "l"(v));
    return r;
}
__device__ __forceinline__ unsigned h2_bits(__half2 h) {
    return *reinterpret_cast<unsigned*>(&h);
}

// ---------------------------------------------------------------------------
// CSR build
// ---------------------------------------------------------------------------
__global__ void k_hist(const int4* __restrict__ dst4, int E4, const int* __restrict__ dst, int E) {
    int i = blockIdx.x * blockDim.x + threadIdx.x;
    if (i < E4) {
        int4 d = __ldg(&dst4[i]);
        atomicAdd(&g_indeg[d.x], 1);
        atomicAdd(&g_indeg[d.y], 1);
        atomicAdd(&g_indeg[d.z], 1);
        atomicAdd(&g_indeg[d.w], 1);
    }
    // tail (E not multiple of 4)
    int t = E4 * 4 + i;
    if (i < (E & 3) && t < E) atomicAdd(&g_indeg[dst[t]], 1);
}

// Inclusive scan of indeg per 1024-block (shfl-based); block totals to g_bsums.
__global__ void k_scan1(int n) {
    __shared__ int wsum[32];
    int t = threadIdx.x, lane = t & 31, w = t >> 5;
    int i = blockIdx.x * 1024 + t;
    int v = (i < n) ? g_indeg[i] : 0;
    int x = v;
    #pragma unroll
    for (int d = 1; d < 32; d <<= 1) {
        int y = __shfl_up_sync(0xffffffffu, x, d);
        if (lane >= d) x += y;
    }
    if (lane == 31) wsum[w] = x;
    __syncthreads();
    if (w == 0) {
        int y = wsum[lane];
        int z = y;
        #pragma unroll
        for (int d = 1; d < 32; d <<= 1) {
            int u = __shfl_up_sync(0xffffffffu, z, d);
            if (lane >= d) z += u;
        }
        wsum[lane] = z - y;  // exclusive
    }
    __syncthreads();
    x += wsum[w];
    if (i < n) g_incl[i] = x;
    if (t == 1023) g_bsums[blockIdx.x] = x;
}

// Parallel exclusive scan of <=128 block sums (1 block, 128 threads).
__global__ void k_scan2(int nb) {
    int t = threadIdx.x;
    int lane = t & 31, w = t >> 5;
    int v = (t < nb) ? g_bsums[t] : 0;
    int x = v;
    #pragma unroll
    for (int d = 1; d < 32; d <<= 1) {
        int y = __shfl_up_sync(0xffffffffu, x, d);
        if (lane >= d) x += y;
    }
    __shared__ int wt[4];
    if (lane == 31) wt[w] = x;
    __syncthreads();
    int add = 0;
    for (int k = 0; k < w; k++) add += wt[k];
    x += add;
    if (t < nb) g_bsums[t] = x - v;   // exclusive
}

// Exclusive offsets + dinv = rsqrt(indeg+1).
__global__ void k_scan3(int n) {
    int i = blockIdx.x * blockDim.x + threadIdx.x;
    if (i < n) {
        int ind = g_indeg[i];
        g_offs[i] = g_incl[i] - ind + g_bsums[i >> 10];
        g_dinv[i] = rsqrtf((float)(ind + 1));
    }
}

// Scatter src indices; atomicAdd shifts g_offs so post-fill offs[v] = range end.
__global__ void k_fill(const int* __restrict__ src, const int* __restrict__ dst, int E) {
    int i = (blockIdx.x * blockDim.x + threadIdx.x) * 4;
    if (i + 4 <= E) {
        int4 s = __ldg((const int4*)(src + i));
        int4 d = __ldg((const int4*)(dst + i));
        g_csr[atomicAdd(&g_offs[d.x], 1)] = s.x;
        g_csr[atomicAdd(&g_offs[d.y], 1)] = s.y;
        g_csr[atomicAdd(&g_offs[d.z], 1)] = s.z;
        g_csr[atomicAdd(&g_offs[d.w], 1)] = s.w;
    } else {
        for (; i < E; i++) {
            g_csr[atomicAdd(&g_offs[dst[i]], 1)] = src[i];
        }
    }
}

// ---------------------------------------------------------------------------
// GEMM + fused dinv-scale + fp16 store: m[r] = fp16(dinv[r] * (X@W)[r]).
// 128 threads/block, 128 rows/block; 8x8 tile/thread via packed f32x2 FMA.
// ---------------------------------------------------------------------------
__global__ __launch_bounds__(128) void k_gemm64h(const float* __restrict__ X,
                                                 const float* __restrict__ W,
                                                 __half* __restrict__ Yh, int n) {
    __shared__ float Ws[64 * 64];
    __shared__ float Xs[128 * 65];  // pad to 65 to avoid bank conflicts

    int t = threadIdx.x;
    #pragma unroll
    for (int i = t; i < 4096; i += 128) Ws[i] = W[i];

    int row0 = blockIdx.x * 128;
    for (int i = t; i < 8192; i += 128) {
        int r = i >> 6, c = i & 63;
        int gr = row0 + r;
        Xs[r * 65 + c] = (gr < n) ? X[gr * 64 + c] : 0.f;
    }
    __syncthreads();

    int cg = t & 7;       // column group: cols [cg*8, cg*8+8)
    int rg = t >> 3;      // row group:    rows [rg*8, rg*8+8)

    unsigned long long acc[8][4];
    #pragma unroll
    for (int i = 0; i < 8; i++)
        #pragma unroll
        for (int j = 0; j < 4; j++) acc[i][j] = 0ull;

    #pragma unroll 4
    for (int k = 0; k < 64; k++) {
        ulonglong2 wA = *(const ulonglong2*)&Ws[k * 64 + cg * 8];
        ulonglong2 wB = *(const ulonglong2*)&Ws[k * 64 + cg * 8 + 4];
        #pragma unroll
        for (int i = 0; i < 8; i++) {
            unsigned long long xp = pack2(Xs[(rg * 8 + i) * 65 + k]);
            ffma2(acc[i][0], xp, wA.x);
            ffma2(acc[i][1], xp, wA.y);
            ffma2(acc[i][2], xp, wB.x);
            ffma2(acc[i][3], xp, wB.y);
        }
    }

    #pragma unroll
    for (int i = 0; i < 8; i++) {
        int gr = row0 + rg * 8 + i;
        if (gr < n) {
            float dv = __ldg(&g_dinv[gr]);
            float2 p0 = unpack2(acc[i][0]), p1 = unpack2(acc[i][1]);
            float2 p2 = unpack2(acc[i][2]), p3 = unpack2(acc[i][3]);
            uint4 pk;
            pk.x = h2_bits(__floats2half2_rn(p0.x * dv, p0.y * dv));
            pk.y = h2_bits(__floats2half2_rn(p1.x * dv, p1.y * dv));
            pk.z = h2_bits(__floats2half2_rn(p2.x * dv, p2.y * dv));
            pk.w = h2_bits(__floats2half2_rn(p3.x * dv, p3.y * dv));
            *(uint4*)&Yh[gr * 64 + cg * 8] = pk;
        }
    }
}

// ---------------------------------------------------------------------------
// Pull aggregation from pre-scaled fp16 messages:
//   acc = m[v] + sum_e m[csr[e]];  out[v] = relu(dinv[v]*acc + bias)
// One warp per node; lane owns half2 columns [2*lane, 2*lane+1].
// Post-fill offs: begin = offs[v-1] (0 for v=0), end = offs[v].
// ---------------------------------------------------------------------------
__global__ __launch_bounds__(256) void k_agg(const __half2* __restrict__ xwh,
                                             const float* __restrict__ bias,
                                             float* __restrict__ out, int n) {
    int v = (blockIdx.x * 256 + threadIdx.x) >> 5;
    int lane = threadIdx.x & 31;
    if (v >= n) return;
    float dv = g_dinv[v];

    float2 sf = __half22float2(__ldg(&xwh[v * 32 + lane]));
    float ax = sf.x, ay = sf.y;   // self-loop message (scale applied at the end)

    int e = (v == 0) ? 0 : __ldg(&g_offs[v - 1]);
    int end = __ldg(&g_offs[v]);

    // 8-deep MLP batches
    for (; e + 8 <= end; e += 8) {
        int s0 = __ldg(&g_csr[e]);
        int s1 = __ldg(&g_csr[e + 1]);
        int s2 = __ldg(&g_csr[e + 2]);
        int s3 = __ldg(&g_csr[e + 3]);
        int s4 = __ldg(&g_csr[e + 4]);
        int s5 = __ldg(&g_csr[e + 5]);
        int s6 = __ldg(&g_csr[e + 6]);
        int s7 = __ldg(&g_csr[e + 7]);
        float2 m0 = __half22float2(__ldg(&xwh[s0 * 32 + lane]));
        float2 m1 = __half22float2(__ldg(&xwh[s1 * 32 + lane]));
        float2 m2 = __half22float2(__ldg(&xwh[s2 * 32 + lane]));
        float2 m3 = __half22float2(__ldg(&xwh[s3 * 32 + lane]));
        float2 m4 = __half22float2(__ldg(&xwh[s4 * 32 + lane]));
        float2 m5 = __half22float2(__ldg(&xwh[s5 * 32 + lane]));
        float2 m6 = __half22float2(__ldg(&xwh[s6 * 32 + lane]));
        float2 m7 = __half22float2(__ldg(&xwh[s7 * 32 + lane]));
        ax += (m0.x + m1.x) + (m2.x + m3.x) + (m4.x + m5.x) + (m6.x + m7.x);
        ay += (m0.y + m1.y) + (m2.y + m3.y) + (m4.y + m5.y) + (m6.y + m7.y);
    }
    // 4-wide
    if (e + 4 <= end) {
        int s0 = __ldg(&g_csr[e]);
        int s1 = __ldg(&g_csr[e + 1]);
        int s2 = __ldg(&g_csr[e + 2]);
        int s3 = __ldg(&g_csr[e + 3]);
        float2 m0 = __half22float2(__ldg(&xwh[s0 * 32 + lane]));
        float2 m1 = __half22float2(__ldg(&xwh[s1 * 32 + lane]));
        float2 m2 = __half22float2(__ldg(&xwh[s2 * 32 + lane]));
        float2 m3 = __half22float2(__ldg(&xwh[s3 * 32 + lane]));
        ax += (m0.x + m1.x) + (m2.x + m3.x);
        ay += (m0.y + m1.y) + (m2.y + m3.y);
        e += 4;
    }
    for (; e < end; e++) {
        int s = __ldg(&g_csr[e]);
        float2 m = __half22float2(__ldg(&xwh[s * 32 + lane]));
        ax += m.x;
        ay += m.y;
    }

    float bx = __ldg(&bias[lane * 2]), by = __ldg(&bias[lane * 2 + 1]);
    float2 r;
    r.x = fmaxf(fmaf(ax, dv, bx), 0.f);
    r.y = fmaxf(fmaf(ay, dv, by), 0.f);
    ((float2*)out)[v * 32 + lane] = r;
}

// ---------------------------------------------------------------------------
extern "C" void kernel_launch(void* const* d_in, const int* in_sizes, int n_in,
                              void* d_out, int out_size) {
    const float* x  = (const float*)d_in[0];
    const int*   ei = (const int*)d_in[1];
    const float* W1 = (const float*)d_in[2];
    const float* b1 = (const float*)d_in[3];
    const float* W2 = (const float*)d_in[4];
    const float* b2 = (const float*)d_in[5];
    float* out = (float*)d_out;

    int N = in_sizes[0] / 64;
    int E = in_sizes[1] / 2;
    const int* src = ei;
    const int* dst = ei + E;
    int E4 = E / 4;

    int nbN = (N + 255) / 256;
    int nbE4 = (E4 + 255) / 256;
    int nbScan = (N + 1023) / 1024;
    int nbAgg = (N + 7) / 8;       // 8 warps per 256-thread block
    int nbGemm = (N + 127) / 128;

    void* indegPtr;     cudaGetSymbolAddress(&indegPtr, g_indeg);
    __half* hbuf;       cudaGetSymbolAddress((void**)&hbuf, g_hbuf);
    float* bufB;        cudaGetSymbolAddress((void**)&bufB, g_bufB);

    // CSR build (per launch -- deterministic work each call)
    cudaMemsetAsync(indegPtr, 0, (size_t)N * sizeof(int));
    k_hist<<<nbE4, 256>>>((const int4*)dst, E4, dst, E);
    k_scan1<<<nbScan, 1024>>>(N);
    k_scan2<<<1, 128>>>(nbScan);
    k_scan3<<<nbN, 256>>>(N);
    // GEMM1 placed here (needs dinv from scan3; independent of fill)
    k_gemm64h<<<nbGemm, 128>>>(x, W1, hbuf, N);
    k_fill<<<nbE4, 256>>>(src, dst, E);

    // Layer 1: h = relu(dinv * Agg(m1) + b1)
    k_agg<<<nbAgg, 256>>>((const __half2*)hbuf, b1, bufB, N);

    // Layer 2: out = relu(dinv * Agg(m2) + b2)
    k_gemm64h<<<nbGemm, 128>>>(bufB, W2, hbuf, N);
    k_agg<<<nbAgg, 256>>>((const __half2*)hbuf, b2, out, N);
}